// round 3
// baseline (speedup 1.0000x reference)
#include <cuda_runtime.h>
#include <math.h>

#define TOKENS 131072
#define CEMB   192
#define NHEAD  6
#define HDIM   32
#define NWIN   2048
#define QSCALE 0.17677669529663687f  // 1/sqrt(32)

// ---------------- scratch (device globals; no runtime allocation) ----------
__device__ float g_xn [(size_t)TOKENS * CEMB];   // LN1(x), window order
__device__ float g_yn [(size_t)TOKENS * CEMB];   // LN1(y), window order
__device__ float g_q  [(size_t)TOKENS * CEMB];   // scaled Q (from y), window order
__device__ float g_kv [(size_t)TOKENS * 2*CEMB]; // [row][0:192]=K, [192:384]=V, window order
__device__ float g_ao [(size_t)TOKENS * CEMB];   // attention out (head-concat), window order
__device__ float g_x1 [(size_t)TOKENS * CEMB];   // x + proj(attn), natural order
__device__ float g_xn2[(size_t)TOKENS * CEMB];   // LN2(x1), natural order
__device__ float g_h  [(size_t)TOKENS * 768];    // MLP hidden

// ---------------- LayerNorm (+ window permutation) -------------------------
// one warp per token; lane handles channels lane, lane+32, ..., lane+160
__device__ __forceinline__ void warp_sum2(float& s, float& ss) {
#pragma unroll
    for (int o = 16; o; o >>= 1) {
        s  += __shfl_xor_sync(0xffffffffu, s,  o);
        ss += __shfl_xor_sync(0xffffffffu, ss, o);
    }
}

__global__ void __launch_bounds__(256) ln_perm_kernel(
    const float* __restrict__ x, const float* __restrict__ y,
    const float* __restrict__ g, const float* __restrict__ b,
    float* __restrict__ xn, float* __restrict__ yn)
{
    int token = blockIdx.x * 8 + (threadIdx.x >> 5);
    int lane  = threadIdx.x & 31;
    int w = token & 63, h = (token >> 6) & 63, d = token >> 12;
    int win  = (((d >> 2) << 4) + (h >> 2)) * 16 + (w >> 2);
    int pos  = ((d & 3) << 4) + ((h & 3) << 2) + (w & 3);
    size_t prow = (size_t)win * 64 + pos;

    float gv[6], bv[6];
#pragma unroll
    for (int i = 0; i < 6; i++) { gv[i] = g[lane + 32*i]; bv[i] = b[lane + 32*i]; }

    const float* xr = x + (size_t)token * CEMB;
    const float* yr = y + (size_t)token * CEMB;
    float* xo = xn + prow * CEMB;
    float* yo = yn + prow * CEMB;

    {
        float v[6], s = 0.f, ss = 0.f;
#pragma unroll
        for (int i = 0; i < 6; i++) { v[i] = xr[lane + 32*i]; s += v[i]; ss += v[i]*v[i]; }
        warp_sum2(s, ss);
        float mean = s * (1.f/192.f);
        float var  = ss * (1.f/192.f) - mean * mean;
        float r = rsqrtf(var + 1e-5f);
#pragma unroll
        for (int i = 0; i < 6; i++) xo[lane + 32*i] = (v[i] - mean) * r * gv[i] + bv[i];
    }
    {
        float v[6], s = 0.f, ss = 0.f;
#pragma unroll
        for (int i = 0; i < 6; i++) { v[i] = yr[lane + 32*i]; s += v[i]; ss += v[i]*v[i]; }
        warp_sum2(s, ss);
        float mean = s * (1.f/192.f);
        float var  = ss * (1.f/192.f) - mean * mean;
        float r = rsqrtf(var + 1e-5f);
#pragma unroll
        for (int i = 0; i < 6; i++) yo[lane + 32*i] = (v[i] - mean) * r * gv[i] + bv[i];
    }
}

__global__ void __launch_bounds__(256) ln_kernel(
    const float* __restrict__ x, const float* __restrict__ g, const float* __restrict__ b,
    float* __restrict__ xn)
{
    int token = blockIdx.x * 8 + (threadIdx.x >> 5);
    int lane  = threadIdx.x & 31;
    const float* xr = x + (size_t)token * CEMB;
    float* xo = xn + (size_t)token * CEMB;
    float v[6], s = 0.f, ss = 0.f;
#pragma unroll
    for (int i = 0; i < 6; i++) { v[i] = xr[lane + 32*i]; s += v[i]; ss += v[i]*v[i]; }
    warp_sum2(s, ss);
    float mean = s * (1.f/192.f);
    float var  = ss * (1.f/192.f) - mean * mean;
    float r = rsqrtf(var + 1e-5f);
#pragma unroll
    for (int i = 0; i < 6; i++)
        xo[lane + 32*i] = (v[i] - mean) * r * g[lane + 32*i] + b[lane + 32*i];
}

// ---------------- generic 64x64x32-tiled SGEMM with fused epilogues --------
// mode 0: C = (acc + bias) * scale
// mode 1: C[perm(row)] = acc + bias + resid[perm(row)]   (window->natural)
// mode 2: C = gelu(acc + bias)
// mode 3: C = acc + bias + resid[row]
__device__ __forceinline__ float gelu_exact(float v) {
    return 0.5f * v * (1.0f + erff(v * 0.70710678118654752f));
}

__global__ void __launch_bounds__(256) gemm_kernel(
    const float* __restrict__ A, const float* __restrict__ B,
    const float* __restrict__ bias, const float* __restrict__ resid,
    float* __restrict__ C,
    int K, int ldb, int ldc, float scale, int mode)
{
    __shared__ float As[32][65];   // transposed A tile, padded (conflict-free)
    __shared__ float Bs[32][64];

    int tid = threadIdx.x;
    int tx = tid & 15, ty = tid >> 4;
    size_t rowBase = (size_t)blockIdx.y * 64;
    int nb = blockIdx.x * 64;

    int lr = tid >> 3;           // A load: row within tile (0..31), +32 for 2nd half
    int lk = (tid & 7) * 4;      // A load: k offset (float4)
    const float* Aptr = A + (rowBase + lr) * (size_t)K + lk;
    int bk = tid >> 3;           // B load: k row (0..31)
    int bn = (tid & 7) * 8;      // B load: 8 floats
    const float* Bptr = B + (size_t)bk * ldb + nb + bn;

    float acc[4][4] = {};

    for (int k0 = 0; k0 < K; k0 += 32) {
        float4 a0 = *(const float4*)(Aptr + k0);
        float4 a1 = *(const float4*)(Aptr + (size_t)32 * K + k0);
        float4 b0 = *(const float4*)(Bptr + (size_t)k0 * ldb);
        float4 b1 = *(const float4*)(Bptr + (size_t)k0 * ldb + 4);

        As[lk+0][lr] = a0.x; As[lk+1][lr] = a0.y; As[lk+2][lr] = a0.z; As[lk+3][lr] = a0.w;
        As[lk+0][lr+32] = a1.x; As[lk+1][lr+32] = a1.y; As[lk+2][lr+32] = a1.z; As[lk+3][lr+32] = a1.w;
        *(float4*)&Bs[bk][bn]     = b0;
        *(float4*)&Bs[bk][bn + 4] = b1;
        __syncthreads();

#pragma unroll
        for (int kk = 0; kk < 32; kk++) {
            float a0v = As[kk][ty*4+0], a1v = As[kk][ty*4+1];
            float a2v = As[kk][ty*4+2], a3v = As[kk][ty*4+3];
            float4 bv = *(const float4*)&Bs[kk][tx*4];
            acc[0][0] += a0v*bv.x; acc[0][1] += a0v*bv.y; acc[0][2] += a0v*bv.z; acc[0][3] += a0v*bv.w;
            acc[1][0] += a1v*bv.x; acc[1][1] += a1v*bv.y; acc[1][2] += a1v*bv.z; acc[1][3] += a1v*bv.w;
            acc[2][0] += a2v*bv.x; acc[2][1] += a2v*bv.y; acc[2][2] += a2v*bv.z; acc[2][3] += a2v*bv.w;
            acc[3][0] += a3v*bv.x; acc[3][1] += a3v*bv.y; acc[3][2] += a3v*bv.z; acc[3][3] += a3v*bv.w;
        }
        __syncthreads();
    }

    int ncol = nb + tx * 4;
    float bb[4];
#pragma unroll
    for (int j = 0; j < 4; j++) bb[j] = bias[ncol + j];

#pragma unroll
    for (int i = 0; i < 4; i++) {
        size_t row = rowBase + ty * 4 + i;
        size_t orow = row;
        if (mode == 1) {
            int win = (int)(row >> 6), pos = (int)(row & 63);
            int wd = win >> 8, wh = (win >> 4) & 15, ww = win & 15;
            int d = (wd << 2) + (pos >> 4);
            int h = (wh << 2) + ((pos >> 2) & 3);
            int w = (ww << 2) + (pos & 3);
            orow = ((size_t)(d * 64 + h)) * 64 + w;
        }
#pragma unroll
        for (int j = 0; j < 4; j++) {
            float v = acc[i][j] + bb[j];
            if (mode == 0)      v *= scale;
            else if (mode == 1) v += resid[orow * CEMB + ncol + j];
            else if (mode == 2) v = gelu_exact(v);
            else                v += resid[row * CEMB + ncol + j];
            C[orow * (size_t)ldc + ncol + j] = v;
        }
    }
}

// ---------------- windowed cross-attention ---------------------------------
// one block per (window, head); 256 threads
__global__ void __launch_bounds__(256) attn_kernel(
    const float* __restrict__ q, const float* __restrict__ kv,
    const float* __restrict__ rpb, float* __restrict__ out)
{
    int win = blockIdx.x, head = blockIdx.y;
    __shared__ float qs[64][33];
    __shared__ float ks[64][33];
    __shared__ float vs[64][33];
    __shared__ float at[64][65];
    __shared__ float bs[343];

    int tid = threadIdx.x;
    const float* qbase = q  + (size_t)win * 64 * CEMB   + head * HDIM;
    const float* kbase = kv + (size_t)win * 64 * 2*CEMB + head * HDIM;
    const float* vbase = kbase + CEMB;

    for (int idx = tid; idx < 64 * 32; idx += 256) {
        int r = idx >> 5, c = idx & 31;
        qs[r][c] = qbase[(size_t)r * CEMB + c];
        ks[r][c] = kbase[(size_t)r * 2*CEMB + c];
        vs[r][c] = vbase[(size_t)r * 2*CEMB + c];
    }
    for (int idx = tid; idx < 343; idx += 256) bs[idx] = rpb[idx * NHEAD + head];
    __syncthreads();

    int i = tid >> 2;                  // query row 0..63
    int jt = tid & 3;                  // 4 lanes cooperate on a row
    int iz = i >> 4, iy = (i >> 2) & 3, ix = i & 3;

    float ev[16];
    float m = -1e30f;
#pragma unroll
    for (int jj = 0; jj < 16; jj++) {
        int j = jt + (jj << 2);        // interleaved j for conflict-free ks reads
        float s = 0.f;
#pragma unroll
        for (int d = 0; d < 32; d++) s += qs[i][d] * ks[j][d];
        int jz = j >> 4, jy = (j >> 2) & 3, jx = j & 3;
        int ridx = (iz - jz + 3) * 49 + (iy - jy + 3) * 7 + (ix - jx + 3);
        s += bs[ridx];
        ev[jj] = s;
        m = fmaxf(m, s);
    }
    m = fmaxf(m, __shfl_xor_sync(0xffffffffu, m, 1));
    m = fmaxf(m, __shfl_xor_sync(0xffffffffu, m, 2));
    float sum = 0.f;
#pragma unroll
    for (int jj = 0; jj < 16; jj++) { ev[jj] = expf(ev[jj] - m); sum += ev[jj]; }
    sum += __shfl_xor_sync(0xffffffffu, sum, 1);
    sum += __shfl_xor_sync(0xffffffffu, sum, 2);
    float rinv = 1.f / sum;
#pragma unroll
    for (int jj = 0; jj < 16; jj++) at[i][jt + (jj << 2)] = ev[jj] * rinv;
    __syncthreads();

    int d0 = jt << 3;                  // 8 output dims per thread
    float o[8] = {};
#pragma unroll
    for (int j = 0; j < 64; j++) {
        float a = at[i][j];
#pragma unroll
        for (int dd = 0; dd < 8; dd++) o[dd] += a * vs[j][d0 + dd];
    }
    float* obase = out + ((size_t)win * 64 + i) * CEMB + head * HDIM + d0;
#pragma unroll
    for (int dd = 0; dd < 8; dd++) obase[dd] = o[dd];
}

// ---------------- launch ----------------------------------------------------
extern "C" void kernel_launch(void* const* d_in, const int* in_sizes, int n_in,
                              void* d_out, int out_size)
{
    const float* x     = (const float*)d_in[0];
    const float* y     = (const float*)d_in[1];
    const float* n1g   = (const float*)d_in[3];
    const float* n1b   = (const float*)d_in[4];
    const float* qkvw  = (const float*)d_in[5];
    const float* qkvb  = (const float*)d_in[6];
    const float* rpb   = (const float*)d_in[7];
    const float* projw = (const float*)d_in[8];
    const float* projb = (const float*)d_in[9];
    const float* n2g   = (const float*)d_in[10];
    const float* n2b   = (const float*)d_in[11];
    const float* fc1w  = (const float*)d_in[12];
    const float* fc1b  = (const float*)d_in[13];
    const float* fc2w  = (const float*)d_in[14];
    const float* fc2b  = (const float*)d_in[15];
    float* out = (float*)d_out;

    float *xn, *yn, *qb, *kvb, *ao, *x1, *xn2, *hb;
    cudaGetSymbolAddress((void**)&xn,  g_xn);
    cudaGetSymbolAddress((void**)&yn,  g_yn);
    cudaGetSymbolAddress((void**)&qb,  g_q);
    cudaGetSymbolAddress((void**)&kvb, g_kv);
    cudaGetSymbolAddress((void**)&ao,  g_ao);
    cudaGetSymbolAddress((void**)&x1,  g_x1);
    cudaGetSymbolAddress((void**)&xn2, g_xn2);
    cudaGetSymbolAddress((void**)&hb,  g_h);

    // 1) LN1 + window permutation for x and y
    ln_perm_kernel<<<TOKENS / 8, 256>>>(x, y, n1g, n1b, xn, yn);

    // 2) Q = (yn @ Wq + bq) * SCALE   (window order)
    gemm_kernel<<<dim3(3, TOKENS / 64), 256>>>(yn, qkvw, qkvb, nullptr, qb,
                                               192, 576, 192, QSCALE, 0);
    // 3) KV = xn @ W[k|v] + b         (window order)
    gemm_kernel<<<dim3(6, TOKENS / 64), 256>>>(xn, qkvw + 192, qkvb + 192, nullptr, kvb,
                                               192, 576, 384, 1.0f, 0);
    // 4) window attention
    attn_kernel<<<dim3(NWIN, NHEAD), 256>>>(qb, kvb, rpb, ao);

    // 5) x1 = x + attn_out @ proj_w + proj_b  (un-permute to natural order)
    gemm_kernel<<<dim3(3, TOKENS / 64), 256>>>(ao, projw, projb, x, x1,
                                               192, 192, 192, 1.0f, 1);
    // 6) LN2
    ln_kernel<<<TOKENS / 8, 256>>>(x1, n2g, n2b, xn2);

    // 7) h = gelu(xn2 @ fc1_w + fc1_b)
    gemm_kernel<<<dim3(12, TOKENS / 64), 256>>>(xn2, fc1w, fc1b, nullptr, hb,
                                                192, 768, 768, 1.0f, 2);
    // 8) out = x1 + h @ fc2_w + fc2_b
    gemm_kernel<<<dim3(3, TOKENS / 64), 256>>>(hb, fc2w, fc2b, x1, out,
                                               768, 192, 192, 1.0f, 3);
}

// round 4
// speedup vs baseline: 2.0966x; 2.0966x over previous
#include <cuda_runtime.h>
#include <math.h>

#define TOKENS 131072
#define CEMB   192
#define NHEAD  6
#define HDIM   32
#define NWIN   2048
#define QSCALE 0.17677669529663687f  // 1/sqrt(32)

// ---------------- scratch (device globals; no runtime allocation) ----------
__device__ float g_xn [(size_t)TOKENS * CEMB];   // LN1(x), window order
__device__ float g_yn [(size_t)TOKENS * CEMB];   // LN1(y), window order
__device__ float g_q  [(size_t)TOKENS * CEMB];   // scaled Q (from y), window order
__device__ float g_kv [(size_t)TOKENS * 2*CEMB]; // [row][0:192]=K, [192:384]=V, window order
__device__ float g_ao [(size_t)TOKENS * CEMB];   // attention out (head-concat), window order
__device__ float g_x1 [(size_t)TOKENS * CEMB];   // x + proj(attn), natural order
__device__ float g_xn2[(size_t)TOKENS * CEMB];   // LN2(x1), natural order
__device__ float g_h  [(size_t)TOKENS * 768];    // MLP hidden

// ---------------- LayerNorm (+ window permutation) -------------------------
__device__ __forceinline__ void warp_sum2(float& s, float& ss) {
#pragma unroll
    for (int o = 16; o; o >>= 1) {
        s  += __shfl_xor_sync(0xffffffffu, s,  o);
        ss += __shfl_xor_sync(0xffffffffu, ss, o);
    }
}

__global__ void __launch_bounds__(256) ln_perm_kernel(
    const float* __restrict__ x, const float* __restrict__ y,
    const float* __restrict__ g, const float* __restrict__ b,
    float* __restrict__ xn, float* __restrict__ yn)
{
    int token = blockIdx.x * 8 + (threadIdx.x >> 5);
    int lane  = threadIdx.x & 31;
    int w = token & 63, h = (token >> 6) & 63, d = token >> 12;
    int win  = (((d >> 2) << 4) + (h >> 2)) * 16 + (w >> 2);
    int pos  = ((d & 3) << 4) + ((h & 3) << 2) + (w & 3);
    size_t prow = (size_t)win * 64 + pos;

    float gv[6], bv[6];
#pragma unroll
    for (int i = 0; i < 6; i++) { gv[i] = g[lane + 32*i]; bv[i] = b[lane + 32*i]; }

    const float* xr = x + (size_t)token * CEMB;
    const float* yr = y + (size_t)token * CEMB;
    float* xo = xn + prow * CEMB;
    float* yo = yn + prow * CEMB;

    {
        float v[6], s = 0.f, ss = 0.f;
#pragma unroll
        for (int i = 0; i < 6; i++) { v[i] = xr[lane + 32*i]; s += v[i]; ss += v[i]*v[i]; }
        warp_sum2(s, ss);
        float mean = s * (1.f/192.f);
        float var  = ss * (1.f/192.f) - mean * mean;
        float r = rsqrtf(var + 1e-5f);
#pragma unroll
        for (int i = 0; i < 6; i++) xo[lane + 32*i] = (v[i] - mean) * r * gv[i] + bv[i];
    }
    {
        float v[6], s = 0.f, ss = 0.f;
#pragma unroll
        for (int i = 0; i < 6; i++) { v[i] = yr[lane + 32*i]; s += v[i]; ss += v[i]*v[i]; }
        warp_sum2(s, ss);
        float mean = s * (1.f/192.f);
        float var  = ss * (1.f/192.f) - mean * mean;
        float r = rsqrtf(var + 1e-5f);
#pragma unroll
        for (int i = 0; i < 6; i++) yo[lane + 32*i] = (v[i] - mean) * r * gv[i] + bv[i];
    }
}

__global__ void __launch_bounds__(256) ln_kernel(
    const float* __restrict__ x, const float* __restrict__ g, const float* __restrict__ b,
    float* __restrict__ xn)
{
    int token = blockIdx.x * 8 + (threadIdx.x >> 5);
    int lane  = threadIdx.x & 31;
    const float* xr = x + (size_t)token * CEMB;
    float* xo = xn + (size_t)token * CEMB;
    float v[6], s = 0.f, ss = 0.f;
#pragma unroll
    for (int i = 0; i < 6; i++) { v[i] = xr[lane + 32*i]; s += v[i]; ss += v[i]*v[i]; }
    warp_sum2(s, ss);
    float mean = s * (1.f/192.f);
    float var  = ss * (1.f/192.f) - mean * mean;
    float r = rsqrtf(var + 1e-5f);
#pragma unroll
    for (int i = 0; i < 6; i++)
        xo[lane + 32*i] = (v[i] - mean) * r * g[lane + 32*i] + b[lane + 32*i];
}

// ---------------- TF32 tensor-core GEMM (m16n8k8 mma.sync) -----------------
// C[M,N] = A[M,K] @ B[K,N] (+bias, fused epilogues)
// CTA tile 128x64, BK=32. 256 threads = 8 warps (2 x 4): warp tile 64x16.
// mode 0: C = (acc + bias) * scale
// mode 1: C[perm(row)] = acc + bias + resid[perm(row)]   (window->natural)
// mode 2: C = gelu(acc + bias)
// mode 3: C = acc + bias + resid[row]
__device__ __forceinline__ float gelu_exact(float v) {
    return 0.5f * v * (1.0f + erff(v * 0.70710678118654752f));
}

__device__ __forceinline__ unsigned f2tf32(float f) {
    unsigned r;
    asm("cvt.rna.tf32.f32 %0, %1;" : "=r"(r) : "f"(f));
    return r;
}

__device__ __forceinline__ void mma_tf32(float* c, const unsigned* a, const unsigned* b) {
    asm volatile(
        "mma.sync.aligned.m16n8k8.row.col.f32.tf32.tf32.f32 "
        "{%0,%1,%2,%3}, {%4,%5,%6,%7}, {%8,%9}, {%0,%1,%2,%3};"
        : "+f"(c[0]), "+f"(c[1]), "+f"(c[2]), "+f"(c[3])
        : "r"(a[0]), "r"(a[1]), "r"(a[2]), "r"(a[3]), "r"(b[0]), "r"(b[1]));
}

__global__ void __launch_bounds__(256) gemm_tf32_kernel(
    const float* __restrict__ A, const float* __restrict__ B,
    const float* __restrict__ bias, const float* __restrict__ resid,
    float* __restrict__ C,
    int K, int ldb, int ldc, float scale, int mode)
{
    __shared__ unsigned As[128][36];   // stride 36: frag reads bank (4g+t) -> conflict-free
    __shared__ unsigned Bs[32][72];    // stride 72: frag reads bank (8t+g) -> conflict-free

    int tid = threadIdx.x;
    int wid = tid >> 5, lane = tid & 31;
    int g = lane >> 2, t = lane & 3;
    int wm = (wid >> 2) * 64;          // warp row offset (0 or 64)
    int wn = (wid & 3) * 16;           // warp col offset
    size_t rowBase = (size_t)blockIdx.y * 128;
    int nb = blockIdx.x * 64;

    // global-load assignments (A: 4 float4/thread, B: 2 float4/thread)
    int ar[4], ac[4];
#pragma unroll
    for (int it = 0; it < 4; it++) { int idx = tid + 256*it; ar[it] = idx >> 3; ac[it] = (idx & 7) * 4; }
    int bkr[2], bcc[2];
#pragma unroll
    for (int it = 0; it < 2; it++) { int idx = tid + 256*it; bkr[it] = idx >> 4; bcc[it] = (idx & 15) * 4; }

    float4 pa[4], pb[2];
#pragma unroll
    for (int it = 0; it < 4; it++)
        pa[it] = *(const float4*)(A + (rowBase + ar[it]) * (size_t)K + ac[it]);
#pragma unroll
    for (int it = 0; it < 2; it++)
        pb[it] = *(const float4*)(B + (size_t)bkr[it] * ldb + nb + bcc[it]);

    float acc[4][2][4] = {};

    for (int k0 = 0; k0 < K; k0 += 32) {
        // stage current tile into smem (convert to tf32)
#pragma unroll
        for (int it = 0; it < 4; it++) {
            As[ar[it]][ac[it]+0] = f2tf32(pa[it].x);
            As[ar[it]][ac[it]+1] = f2tf32(pa[it].y);
            As[ar[it]][ac[it]+2] = f2tf32(pa[it].z);
            As[ar[it]][ac[it]+3] = f2tf32(pa[it].w);
        }
#pragma unroll
        for (int it = 0; it < 2; it++) {
            Bs[bkr[it]][bcc[it]+0] = f2tf32(pb[it].x);
            Bs[bkr[it]][bcc[it]+1] = f2tf32(pb[it].y);
            Bs[bkr[it]][bcc[it]+2] = f2tf32(pb[it].z);
            Bs[bkr[it]][bcc[it]+3] = f2tf32(pb[it].w);
        }
        __syncthreads();

        // prefetch next tile (hidden behind mma block)
        if (k0 + 32 < K) {
            int kn = k0 + 32;
#pragma unroll
            for (int it = 0; it < 4; it++)
                pa[it] = *(const float4*)(A + (rowBase + ar[it]) * (size_t)K + kn + ac[it]);
#pragma unroll
            for (int it = 0; it < 2; it++)
                pb[it] = *(const float4*)(B + (size_t)(kn + bkr[it]) * ldb + nb + bcc[it]);
        }

#pragma unroll
        for (int ks = 0; ks < 4; ks++) {
            int kk = ks * 8;
            unsigned bf[2][2];
#pragma unroll
            for (int nf = 0; nf < 2; nf++) {
                bf[nf][0] = Bs[kk + t    ][wn + nf*8 + g];
                bf[nf][1] = Bs[kk + t + 4][wn + nf*8 + g];
            }
#pragma unroll
            for (int mf = 0; mf < 4; mf++) {
                int r0 = wm + mf*16 + g;
                unsigned af[4];
                af[0] = As[r0    ][kk + t];
                af[1] = As[r0 + 8][kk + t];
                af[2] = As[r0    ][kk + t + 4];
                af[3] = As[r0 + 8][kk + t + 4];
                mma_tf32(acc[mf][0], af, bf[0]);
                mma_tf32(acc[mf][1], af, bf[1]);
            }
        }
        __syncthreads();
    }

    // ---------------- epilogue ----------------
#pragma unroll
    for (int mf = 0; mf < 4; mf++) {
#pragma unroll
        for (int half = 0; half < 2; half++) {
            size_t row = rowBase + wm + mf*16 + g + half*8;
            size_t orow = row;
            if (mode == 1) {
                int win = (int)(row >> 6), pos = (int)(row & 63);
                int wd = win >> 8, wh = (win >> 4) & 15, ww = win & 15;
                int d = (wd << 2) + (pos >> 4);
                int h = (wh << 2) + ((pos >> 2) & 3);
                int w = (ww << 2) + (pos & 3);
                orow = ((size_t)(d * 64 + h)) * 64 + w;
            }
#pragma unroll
            for (int nf = 0; nf < 2; nf++) {
                int col = nb + wn + nf*8 + 2*t;
                float v0 = acc[mf][nf][half*2+0] + bias[col];
                float v1 = acc[mf][nf][half*2+1] + bias[col+1];
                if (mode == 0) { v0 *= scale; v1 *= scale; }
                else if (mode == 1) {
                    v0 += resid[orow * CEMB + col];
                    v1 += resid[orow * CEMB + col + 1];
                } else if (mode == 2) {
                    v0 = gelu_exact(v0); v1 = gelu_exact(v1);
                } else {
                    v0 += resid[row * CEMB + col];
                    v1 += resid[row * CEMB + col + 1];
                }
                float2 o = make_float2(v0, v1);
                *(float2*)(C + orow * (size_t)ldc + col) = o;
            }
        }
    }
}

// ---------------- windowed cross-attention ---------------------------------
__global__ void __launch_bounds__(256) attn_kernel(
    const float* __restrict__ q, const float* __restrict__ kv,
    const float* __restrict__ rpb, float* __restrict__ out)
{
    int win = blockIdx.x, head = blockIdx.y;
    __shared__ float qs[64][33];
    __shared__ float ks[64][33];
    __shared__ float vs[64][33];
    __shared__ float at[64][65];
    __shared__ float bs[343];

    int tid = threadIdx.x;
    const float* qbase = q  + (size_t)win * 64 * CEMB   + head * HDIM;
    const float* kbase = kv + (size_t)win * 64 * 2*CEMB + head * HDIM;
    const float* vbase = kbase + CEMB;

    for (int idx = tid; idx < 64 * 32; idx += 256) {
        int r = idx >> 5, c = idx & 31;
        qs[r][c] = qbase[(size_t)r * CEMB + c];
        ks[r][c] = kbase[(size_t)r * 2*CEMB + c];
        vs[r][c] = vbase[(size_t)r * 2*CEMB + c];
    }
    for (int idx = tid; idx < 343; idx += 256) bs[idx] = rpb[idx * NHEAD + head];
    __syncthreads();

    int i = tid >> 2;
    int jt = tid & 3;
    int iz = i >> 4, iy = (i >> 2) & 3, ix = i & 3;

    float ev[16];
    float m = -1e30f;
#pragma unroll
    for (int jj = 0; jj < 16; jj++) {
        int j = jt + (jj << 2);
        float s = 0.f;
#pragma unroll
        for (int d = 0; d < 32; d++) s += qs[i][d] * ks[j][d];
        int jz = j >> 4, jy = (j >> 2) & 3, jx = j & 3;
        int ridx = (iz - jz + 3) * 49 + (iy - jy + 3) * 7 + (ix - jx + 3);
        s += bs[ridx];
        ev[jj] = s;
        m = fmaxf(m, s);
    }
    m = fmaxf(m, __shfl_xor_sync(0xffffffffu, m, 1));
    m = fmaxf(m, __shfl_xor_sync(0xffffffffu, m, 2));
    float sum = 0.f;
#pragma unroll
    for (int jj = 0; jj < 16; jj++) { ev[jj] = expf(ev[jj] - m); sum += ev[jj]; }
    sum += __shfl_xor_sync(0xffffffffu, sum, 1);
    sum += __shfl_xor_sync(0xffffffffu, sum, 2);
    float rinv = 1.f / sum;
#pragma unroll
    for (int jj = 0; jj < 16; jj++) at[i][jt + (jj << 2)] = ev[jj] * rinv;
    __syncthreads();

    int d0 = jt << 3;
    float o[8] = {};
#pragma unroll
    for (int j = 0; j < 64; j++) {
        float a = at[i][j];
#pragma unroll
        for (int dd = 0; dd < 8; dd++) o[dd] += a * vs[j][d0 + dd];
    }
    float* obase = out + ((size_t)win * 64 + i) * CEMB + head * HDIM + d0;
#pragma unroll
    for (int dd = 0; dd < 8; dd++) obase[dd] = o[dd];
}

// ---------------- launch ----------------------------------------------------
extern "C" void kernel_launch(void* const* d_in, const int* in_sizes, int n_in,
                              void* d_out, int out_size)
{
    const float* x     = (const float*)d_in[0];
    const float* y     = (const float*)d_in[1];
    const float* n1g   = (const float*)d_in[3];
    const float* n1b   = (const float*)d_in[4];
    const float* qkvw  = (const float*)d_in[5];
    const float* qkvb  = (const float*)d_in[6];
    const float* rpb   = (const float*)d_in[7];
    const float* projw = (const float*)d_in[8];
    const float* projb = (const float*)d_in[9];
    const float* n2g   = (const float*)d_in[10];
    const float* n2b   = (const float*)d_in[11];
    const float* fc1w  = (const float*)d_in[12];
    const float* fc1b  = (const float*)d_in[13];
    const float* fc2w  = (const float*)d_in[14];
    const float* fc2b  = (const float*)d_in[15];
    float* out = (float*)d_out;

    float *xn, *yn, *qb, *kvb, *ao, *x1, *xn2, *hb;
    cudaGetSymbolAddress((void**)&xn,  g_xn);
    cudaGetSymbolAddress((void**)&yn,  g_yn);
    cudaGetSymbolAddress((void**)&qb,  g_q);
    cudaGetSymbolAddress((void**)&kvb, g_kv);
    cudaGetSymbolAddress((void**)&ao,  g_ao);
    cudaGetSymbolAddress((void**)&x1,  g_x1);
    cudaGetSymbolAddress((void**)&xn2, g_xn2);
    cudaGetSymbolAddress((void**)&hb,  g_h);

    // 1) LN1 + window permutation for x and y
    ln_perm_kernel<<<TOKENS / 8, 256>>>(x, y, n1g, n1b, xn, yn);

    // 2) Q = (yn @ Wq + bq) * SCALE   (window order)
    gemm_tf32_kernel<<<dim3(3, TOKENS / 128), 256>>>(yn, qkvw, qkvb, nullptr, qb,
                                                     192, 576, 192, QSCALE, 0);
    // 3) KV = xn @ W[k|v] + b         (window order)
    gemm_tf32_kernel<<<dim3(6, TOKENS / 128), 256>>>(xn, qkvw + 192, qkvb + 192, nullptr, kvb,
                                                     192, 576, 384, 1.0f, 0);
    // 4) window attention
    attn_kernel<<<dim3(NWIN, NHEAD), 256>>>(qb, kvb, rpb, ao);

    // 5) x1 = x + attn_out @ proj_w + proj_b  (un-permute to natural order)
    gemm_tf32_kernel<<<dim3(3, TOKENS / 128), 256>>>(ao, projw, projb, x, x1,
                                                     192, 192, 192, 1.0f, 1);
    // 6) LN2
    ln_kernel<<<TOKENS / 8, 256>>>(x1, n2g, n2b, xn2);

    // 7) h = gelu(xn2 @ fc1_w + fc1_b)
    gemm_tf32_kernel<<<dim3(12, TOKENS / 128), 256>>>(xn2, fc1w, fc1b, nullptr, hb,
                                                      192, 768, 768, 1.0f, 2);
    // 8) out = x1 + h @ fc2_w + fc2_b
    gemm_tf32_kernel<<<dim3(3, TOKENS / 128), 256>>>(hb, fc2w, fc2b, x1, out,
                                                     768, 192, 192, 1.0f, 3);
}

// round 5
// speedup vs baseline: 2.7062x; 1.2908x over previous
#include <cuda_runtime.h>
#include <math.h>

#define TOKENS 131072
#define CEMB   192
#define NHEAD  6
#define HDIM   32
#define NWIN   2048
#define QSCALE 0.17677669529663687f  // 1/sqrt(32)

// ---------------- scratch (device globals; no runtime allocation) ----------
__device__ float g_xn [(size_t)TOKENS * CEMB];   // LN1(x), window order
__device__ float g_yn [(size_t)TOKENS * CEMB];   // LN1(y), window order
__device__ float g_q  [(size_t)TOKENS * CEMB];   // scaled Q (from y), window order
__device__ float g_kv [(size_t)TOKENS * 2*CEMB]; // [row][0:192]=K, [192:384]=V, window order
__device__ float g_ao [(size_t)TOKENS * CEMB];   // attention out (head-concat), window order
__device__ float g_x1 [(size_t)TOKENS * CEMB];   // x + proj(attn), natural order
__device__ float g_xn2[(size_t)TOKENS * CEMB];   // LN2(x1), natural order
__device__ float g_h  [(size_t)TOKENS * 768];    // MLP hidden

// ---------------- LayerNorm (+ window permutation) -------------------------
__device__ __forceinline__ void warp_sum2(float& s, float& ss) {
#pragma unroll
    for (int o = 16; o; o >>= 1) {
        s  += __shfl_xor_sync(0xffffffffu, s,  o);
        ss += __shfl_xor_sync(0xffffffffu, ss, o);
    }
}

__global__ void __launch_bounds__(256) ln_perm_kernel(
    const float* __restrict__ x, const float* __restrict__ y,
    const float* __restrict__ g, const float* __restrict__ b,
    float* __restrict__ xn, float* __restrict__ yn)
{
    int token = blockIdx.x * 8 + (threadIdx.x >> 5);
    int lane  = threadIdx.x & 31;
    int w = token & 63, h = (token >> 6) & 63, d = token >> 12;
    int win  = (((d >> 2) << 4) + (h >> 2)) * 16 + (w >> 2);
    int pos  = ((d & 3) << 4) + ((h & 3) << 2) + (w & 3);
    size_t prow = (size_t)win * 64 + pos;

    float gv[6], bv[6];
#pragma unroll
    for (int i = 0; i < 6; i++) { gv[i] = g[lane + 32*i]; bv[i] = b[lane + 32*i]; }

    const float* xr = x + (size_t)token * CEMB;
    const float* yr = y + (size_t)token * CEMB;
    float* xo = xn + prow * CEMB;
    float* yo = yn + prow * CEMB;

    {
        float v[6], s = 0.f, ss = 0.f;
#pragma unroll
        for (int i = 0; i < 6; i++) { v[i] = xr[lane + 32*i]; s += v[i]; ss += v[i]*v[i]; }
        warp_sum2(s, ss);
        float mean = s * (1.f/192.f);
        float var  = ss * (1.f/192.f) - mean * mean;
        float r = rsqrtf(var + 1e-5f);
#pragma unroll
        for (int i = 0; i < 6; i++) xo[lane + 32*i] = (v[i] - mean) * r * gv[i] + bv[i];
    }
    {
        float v[6], s = 0.f, ss = 0.f;
#pragma unroll
        for (int i = 0; i < 6; i++) { v[i] = yr[lane + 32*i]; s += v[i]; ss += v[i]*v[i]; }
        warp_sum2(s, ss);
        float mean = s * (1.f/192.f);
        float var  = ss * (1.f/192.f) - mean * mean;
        float r = rsqrtf(var + 1e-5f);
#pragma unroll
        for (int i = 0; i < 6; i++) yo[lane + 32*i] = (v[i] - mean) * r * gv[i] + bv[i];
    }
}

__global__ void __launch_bounds__(256) ln_kernel(
    const float* __restrict__ x, const float* __restrict__ g, const float* __restrict__ b,
    float* __restrict__ xn)
{
    int token = blockIdx.x * 8 + (threadIdx.x >> 5);
    int lane  = threadIdx.x & 31;
    const float* xr = x + (size_t)token * CEMB;
    float* xo = xn + (size_t)token * CEMB;
    float v[6], s = 0.f, ss = 0.f;
#pragma unroll
    for (int i = 0; i < 6; i++) { v[i] = xr[lane + 32*i]; s += v[i]; ss += v[i]*v[i]; }
    warp_sum2(s, ss);
    float mean = s * (1.f/192.f);
    float var  = ss * (1.f/192.f) - mean * mean;
    float r = rsqrtf(var + 1e-5f);
#pragma unroll
    for (int i = 0; i < 6; i++)
        xo[lane + 32*i] = (v[i] - mean) * r * g[lane + 32*i] + b[lane + 32*i];
}

// ---------------- TF32 helpers ---------------------------------------------
__device__ __forceinline__ float gelu_exact(float v) {
    return 0.5f * v * (1.0f + erff(v * 0.70710678118654752f));
}

__device__ __forceinline__ unsigned f2tf32(float f) {
    unsigned r;
    asm("cvt.rna.tf32.f32 %0, %1;" : "=r"(r) : "f"(f));
    return r;
}

__device__ __forceinline__ void mma_tf32(float* c, const unsigned* a, const unsigned* b) {
    asm volatile(
        "mma.sync.aligned.m16n8k8.row.col.f32.tf32.tf32.f32 "
        "{%0,%1,%2,%3}, {%4,%5,%6,%7}, {%8,%9}, {%0,%1,%2,%3};"
        : "+f"(c[0]), "+f"(c[1]), "+f"(c[2]), "+f"(c[3])
        : "r"(a[0]), "r"(a[1]), "r"(a[2]), "r"(a[3]), "r"(b[0]), "r"(b[1]));
}

// ---------------- TF32 tensor-core GEMM ------------------------------------
// CTA tile 128 x (4*WN), BK=32; 256 threads = 8 warps (2 x 4), warp tile 64 x WN.
// mode 0: C=(acc+bias)*scale; 1: window->natural permute + resid; 2: gelu; 3: +resid
template<int WN>
__global__ void __launch_bounds__(256) gemm_tf32_kernel(
    const float* __restrict__ A, const float* __restrict__ B,
    const float* __restrict__ bias, const float* __restrict__ resid,
    float* __restrict__ C,
    int K, int ldb, int ldc, float scale, int mode)
{
    constexpr int BN  = WN * 4;
    constexpr int LDB = (WN == 16) ? 72 : 132;   // conflict-free frag reads
    constexpr int NF  = WN / 8;
    constexpr int BIT = BN / 32;                  // B float4 loads per thread

    __shared__ unsigned As[128][36];
    __shared__ unsigned Bs[32][LDB];

    int tid = threadIdx.x;
    int wid = tid >> 5, lane = tid & 31;
    int g = lane >> 2, t = lane & 3;
    int wm = (wid >> 2) * 64;
    int wn = (wid & 3) * WN;
    size_t rowBase = (size_t)blockIdx.y * 128;
    int nb = blockIdx.x * BN;

    int ar[4], ac[4];
#pragma unroll
    for (int it = 0; it < 4; it++) { int idx = tid + 256*it; ar[it] = idx >> 3; ac[it] = (idx & 7) * 4; }
    int bkr[BIT], bcc[BIT];
#pragma unroll
    for (int it = 0; it < BIT; it++) {
        int idx = tid + 256*it;
        bkr[it] = idx / (BN/4);
        bcc[it] = (idx % (BN/4)) * 4;
    }

    float4 pa[4], pb[BIT];
#pragma unroll
    for (int it = 0; it < 4; it++)
        pa[it] = *(const float4*)(A + (rowBase + ar[it]) * (size_t)K + ac[it]);
#pragma unroll
    for (int it = 0; it < BIT; it++)
        pb[it] = *(const float4*)(B + (size_t)bkr[it] * ldb + nb + bcc[it]);

    float acc[4][NF][4] = {};

    for (int k0 = 0; k0 < K; k0 += 32) {
#pragma unroll
        for (int it = 0; it < 4; it++) {
            As[ar[it]][ac[it]+0] = f2tf32(pa[it].x);
            As[ar[it]][ac[it]+1] = f2tf32(pa[it].y);
            As[ar[it]][ac[it]+2] = f2tf32(pa[it].z);
            As[ar[it]][ac[it]+3] = f2tf32(pa[it].w);
        }
#pragma unroll
        for (int it = 0; it < BIT; it++) {
            Bs[bkr[it]][bcc[it]+0] = f2tf32(pb[it].x);
            Bs[bkr[it]][bcc[it]+1] = f2tf32(pb[it].y);
            Bs[bkr[it]][bcc[it]+2] = f2tf32(pb[it].z);
            Bs[bkr[it]][bcc[it]+3] = f2tf32(pb[it].w);
        }
        __syncthreads();

        if (k0 + 32 < K) {
            int kn = k0 + 32;
#pragma unroll
            for (int it = 0; it < 4; it++)
                pa[it] = *(const float4*)(A + (rowBase + ar[it]) * (size_t)K + kn + ac[it]);
#pragma unroll
            for (int it = 0; it < BIT; it++)
                pb[it] = *(const float4*)(B + (size_t)(kn + bkr[it]) * ldb + nb + bcc[it]);
        }

#pragma unroll
        for (int ks = 0; ks < 4; ks++) {
            int kk = ks * 8;
            unsigned bf[NF][2];
#pragma unroll
            for (int nf = 0; nf < NF; nf++) {
                bf[nf][0] = Bs[kk + t    ][wn + nf*8 + g];
                bf[nf][1] = Bs[kk + t + 4][wn + nf*8 + g];
            }
#pragma unroll
            for (int mf = 0; mf < 4; mf++) {
                int r0 = wm + mf*16 + g;
                unsigned af[4];
                af[0] = As[r0    ][kk + t];
                af[1] = As[r0 + 8][kk + t];
                af[2] = As[r0    ][kk + t + 4];
                af[3] = As[r0 + 8][kk + t + 4];
#pragma unroll
                for (int nf = 0; nf < NF; nf++) mma_tf32(acc[mf][nf], af, bf[nf]);
            }
        }
        __syncthreads();
    }

#pragma unroll
    for (int mf = 0; mf < 4; mf++) {
#pragma unroll
        for (int half = 0; half < 2; half++) {
            size_t row = rowBase + wm + mf*16 + g + half*8;
            size_t orow = row;
            if (mode == 1) {
                int win = (int)(row >> 6), pos = (int)(row & 63);
                int wd = win >> 8, wh = (win >> 4) & 15, ww = win & 15;
                int d = (wd << 2) + (pos >> 4);
                int h = (wh << 2) + ((pos >> 2) & 3);
                int w = (ww << 2) + (pos & 3);
                orow = ((size_t)(d * 64 + h)) * 64 + w;
            }
#pragma unroll
            for (int nf = 0; nf < NF; nf++) {
                int col = nb + wn + nf*8 + 2*t;
                float v0 = acc[mf][nf][half*2+0] + bias[col];
                float v1 = acc[mf][nf][half*2+1] + bias[col+1];
                if (mode == 0) { v0 *= scale; v1 *= scale; }
                else if (mode == 1) {
                    v0 += resid[orow * CEMB + col];
                    v1 += resid[orow * CEMB + col + 1];
                } else if (mode == 2) {
                    v0 = gelu_exact(v0); v1 = gelu_exact(v1);
                } else {
                    v0 += resid[row * CEMB + col];
                    v1 += resid[row * CEMB + col + 1];
                }
                float2 o = make_float2(v0, v1);
                *(float2*)(C + orow * (size_t)ldc + col) = o;
            }
        }
    }
}

// ---------------- tensor-core windowed cross-attention ---------------------
// one block per (window, head); 128 threads (4 warps, 16 rows each)
// S = Q K^T (64x64x32) -> bias + softmax in registers -> O = P V (64x64x64)
__global__ void __launch_bounds__(128) attn_mma_kernel(
    const float* __restrict__ q, const float* __restrict__ kv,
    const float* __restrict__ rpb, float* __restrict__ out)
{
    __shared__ unsigned sm_qk[64 * 36 * 2];   // Qs | Ks; reused as Ps[64][68]
    __shared__ unsigned sm_v [64 * 36];
    __shared__ float    sm_b [343];

    unsigned (*Qs)[36] = (unsigned(*)[36])sm_qk;
    unsigned (*Ks)[36] = (unsigned(*)[36])(sm_qk + 64*36);
    unsigned (*Ps)[68] = (unsigned(*)[68])sm_qk;          // 64*68 <= 64*72
    unsigned (*Vs)[36] = (unsigned(*)[36])sm_v;           // [k=j][n=d]

    int win = blockIdx.x, head = blockIdx.y;
    int tid = threadIdx.x;
    int wid = tid >> 5, lane = tid & 31;
    int g = lane >> 2, t = lane & 3;

    const float* qbase = q  + (size_t)win * 64 * CEMB   + head * HDIM;
    const float* kbase = kv + (size_t)win * 64 * 2*CEMB + head * HDIM;
    const float* vbase = kbase + CEMB;

    for (int idx = tid; idx < 64 * 32; idx += 128) {
        int r = idx >> 5, c = idx & 31;
        Qs[r][c] = f2tf32(qbase[(size_t)r * CEMB   + c]);
        Ks[r][c] = f2tf32(kbase[(size_t)r * 2*CEMB + c]);
        Vs[r][c] = f2tf32(vbase[(size_t)r * 2*CEMB + c]);
    }
    for (int idx = tid; idx < 343; idx += 128) sm_b[idx] = rpb[idx * NHEAD + head];
    __syncthreads();

    // ---- S = Q K^T ----
    int r0 = wid * 16;
    float sacc[8][4] = {};
#pragma unroll
    for (int ks = 0; ks < 4; ks++) {
        int kk = ks * 8;
        unsigned af[4];
        af[0] = Qs[r0 + g    ][kk + t];
        af[1] = Qs[r0 + g + 8][kk + t];
        af[2] = Qs[r0 + g    ][kk + t + 4];
        af[3] = Qs[r0 + g + 8][kk + t + 4];
#pragma unroll
        for (int nt = 0; nt < 8; nt++) {
            unsigned bf[2];
            bf[0] = Ks[nt*8 + g][kk + t];
            bf[1] = Ks[nt*8 + g][kk + t + 4];
            mma_tf32(sacc[nt], af, bf);
        }
    }
    __syncthreads();   // everyone done reading Qs/Ks before Ps overwrites

    // ---- bias + softmax (rows rA = r0+g, rB = rA+8) ----
    int rA = r0 + g, rB = rA + 8;
    int iz = wid;
    int iyA = (rA >> 2) & 3, ixA = rA & 3;
    int iyB = (rB >> 2) & 3, ixB = rB & 3;

    float vA[16], vB[16];
    float mA = -1e30f, mB = -1e30f;
#pragma unroll
    for (int nt = 0; nt < 8; nt++) {
#pragma unroll
        for (int e = 0; e < 2; e++) {
            int j = nt*8 + 2*t + e;
            int jz = j >> 4, jy = (j >> 2) & 3, jx = j & 3;
            int base = (iz - jz + 3) * 49;
            float a = sacc[nt][e]     + sm_b[base + (iyA - jy + 3) * 7 + (ixA - jx + 3)];
            float b = sacc[nt][2 + e] + sm_b[base + (iyB - jy + 3) * 7 + (ixB - jx + 3)];
            vA[nt*2+e] = a; mA = fmaxf(mA, a);
            vB[nt*2+e] = b; mB = fmaxf(mB, b);
        }
    }
    mA = fmaxf(mA, __shfl_xor_sync(0xffffffffu, mA, 1));
    mA = fmaxf(mA, __shfl_xor_sync(0xffffffffu, mA, 2));
    mB = fmaxf(mB, __shfl_xor_sync(0xffffffffu, mB, 1));
    mB = fmaxf(mB, __shfl_xor_sync(0xffffffffu, mB, 2));

    float sA = 0.f, sB = 0.f;
#pragma unroll
    for (int i = 0; i < 16; i++) {
        vA[i] = __expf(vA[i] - mA); sA += vA[i];
        vB[i] = __expf(vB[i] - mB); sB += vB[i];
    }
    sA += __shfl_xor_sync(0xffffffffu, sA, 1);
    sA += __shfl_xor_sync(0xffffffffu, sA, 2);
    sB += __shfl_xor_sync(0xffffffffu, sB, 1);
    sB += __shfl_xor_sync(0xffffffffu, sB, 2);
    float rAi = 1.f / sA, rBi = 1.f / sB;

#pragma unroll
    for (int nt = 0; nt < 8; nt++) {
#pragma unroll
        for (int e = 0; e < 2; e++) {
            int j = nt*8 + 2*t + e;
            Ps[rA][j] = f2tf32(vA[nt*2+e] * rAi);
            Ps[rB][j] = f2tf32(vB[nt*2+e] * rBi);
        }
    }
    __syncwarp();   // each warp reads only its own 16 Ps rows

    // ---- O = P V ----
    float oacc[4][4] = {};
#pragma unroll
    for (int ks = 0; ks < 8; ks++) {
        int kk = ks * 8;
        unsigned af[4];
        af[0] = Ps[r0 + g    ][kk + t];
        af[1] = Ps[r0 + g + 8][kk + t];
        af[2] = Ps[r0 + g    ][kk + t + 4];
        af[3] = Ps[r0 + g + 8][kk + t + 4];
#pragma unroll
        for (int nt = 0; nt < 4; nt++) {
            unsigned bf[2];
            bf[0] = Vs[kk + t    ][nt*8 + g];
            bf[1] = Vs[kk + t + 4][nt*8 + g];
            mma_tf32(oacc[nt], af, bf);
        }
    }

    float* obase = out + (size_t)win * 64 * CEMB + head * HDIM;
#pragma unroll
    for (int nt = 0; nt < 4; nt++) {
        int c = nt*8 + 2*t;
        *(float2*)&obase[(size_t)rA * CEMB + c] = make_float2(oacc[nt][0], oacc[nt][1]);
        *(float2*)&obase[(size_t)rB * CEMB + c] = make_float2(oacc[nt][2], oacc[nt][3]);
    }
}

// ---------------- launch ----------------------------------------------------
extern "C" void kernel_launch(void* const* d_in, const int* in_sizes, int n_in,
                              void* d_out, int out_size)
{
    const float* x     = (const float*)d_in[0];
    const float* y     = (const float*)d_in[1];
    const float* n1g   = (const float*)d_in[3];
    const float* n1b   = (const float*)d_in[4];
    const float* qkvw  = (const float*)d_in[5];
    const float* qkvb  = (const float*)d_in[6];
    const float* rpb   = (const float*)d_in[7];
    const float* projw = (const float*)d_in[8];
    const float* projb = (const float*)d_in[9];
    const float* n2g   = (const float*)d_in[10];
    const float* n2b   = (const float*)d_in[11];
    const float* fc1w  = (const float*)d_in[12];
    const float* fc1b  = (const float*)d_in[13];
    const float* fc2w  = (const float*)d_in[14];
    const float* fc2b  = (const float*)d_in[15];
    float* out = (float*)d_out;

    float *xn, *yn, *qb, *kvb, *ao, *x1, *xn2, *hb;
    cudaGetSymbolAddress((void**)&xn,  g_xn);
    cudaGetSymbolAddress((void**)&yn,  g_yn);
    cudaGetSymbolAddress((void**)&qb,  g_q);
    cudaGetSymbolAddress((void**)&kvb, g_kv);
    cudaGetSymbolAddress((void**)&ao,  g_ao);
    cudaGetSymbolAddress((void**)&x1,  g_x1);
    cudaGetSymbolAddress((void**)&xn2, g_xn2);
    cudaGetSymbolAddress((void**)&hb,  g_h);

    // 1) LN1 + window permutation for x and y
    ln_perm_kernel<<<TOKENS / 8, 256>>>(x, y, n1g, n1b, xn, yn);

    // 2) Q = (yn @ Wq + bq) * SCALE   (window order)
    gemm_tf32_kernel<16><<<dim3(3, TOKENS / 128), 256>>>(yn, qkvw, qkvb, nullptr, qb,
                                                         192, 576, 192, QSCALE, 0);
    // 3) KV = xn @ W[k|v] + b         (window order)
    gemm_tf32_kernel<16><<<dim3(6, TOKENS / 128), 256>>>(xn, qkvw + 192, qkvb + 192, nullptr, kvb,
                                                         192, 576, 384, 1.0f, 0);
    // 4) window attention (tensor cores)
    attn_mma_kernel<<<dim3(NWIN, NHEAD), 128>>>(qb, kvb, rpb, ao);

    // 5) x1 = x + attn_out @ proj_w + proj_b  (un-permute to natural order)
    gemm_tf32_kernel<16><<<dim3(3, TOKENS / 128), 256>>>(ao, projw, projb, x, x1,
                                                         192, 192, 192, 1.0f, 1);
    // 6) LN2
    ln_kernel<<<TOKENS / 8, 256>>>(x1, n2g, n2b, xn2);

    // 7) h = gelu(xn2 @ fc1_w + fc1_b)   (wide-N tile)
    gemm_tf32_kernel<32><<<dim3(6, TOKENS / 128), 256>>>(xn2, fc1w, fc1b, nullptr, hb,
                                                         192, 768, 768, 1.0f, 2);
    // 8) out = x1 + h @ fc2_w + fc2_b
    gemm_tf32_kernel<16><<<dim3(3, TOKENS / 128), 256>>>(hb, fc2w, fc2b, x1, out,
                                                         768, 192, 192, 1.0f, 3);
}

// round 6
// speedup vs baseline: 3.4804x; 1.2861x over previous
#include <cuda_runtime.h>
#include <math.h>

#define TOKENS 131072
#define CEMB   192
#define NHEAD  6
#define HDIM   32
#define NWIN   2048
#define QSCALE 0.17677669529663687f  // 1/sqrt(32)

// ---------------- scratch (device globals; no runtime allocation) ----------
__device__ float g_xn [(size_t)TOKENS * CEMB];   // LN1(x), window order
__device__ float g_yn [(size_t)TOKENS * CEMB];   // LN1(y), window order
__device__ float g_q  [(size_t)TOKENS * CEMB];   // scaled Q (from y), window order
__device__ float g_kv [(size_t)TOKENS * 2*CEMB]; // [row][0:192]=K, [192:384]=V, window order
__device__ float g_ao [(size_t)TOKENS * CEMB];   // attention out (head-concat), window order
__device__ float g_x1 [(size_t)TOKENS * CEMB];   // x + proj(attn), natural order
__device__ float g_xn2[(size_t)TOKENS * CEMB];   // LN2(x1), natural order
__device__ float g_h  [(size_t)TOKENS * 768];    // MLP hidden
__device__ float g_bias[NHEAD * 64 * 64];        // expanded relative-position bias

// ---------------- LayerNorm (+ window permutation) -------------------------
__device__ __forceinline__ void warp_sum2(float& s, float& ss) {
#pragma unroll
    for (int o = 16; o; o >>= 1) {
        s  += __shfl_xor_sync(0xffffffffu, s,  o);
        ss += __shfl_xor_sync(0xffffffffu, ss, o);
    }
}

__global__ void __launch_bounds__(256) ln_perm_kernel(
    const float* __restrict__ x, const float* __restrict__ y,
    const float* __restrict__ g, const float* __restrict__ b,
    float* __restrict__ xn, float* __restrict__ yn)
{
    int token = blockIdx.x * 8 + (threadIdx.x >> 5);
    int lane  = threadIdx.x & 31;
    int w = token & 63, h = (token >> 6) & 63, d = token >> 12;
    int win  = (((d >> 2) << 4) + (h >> 2)) * 16 + (w >> 2);
    int pos  = ((d & 3) << 4) + ((h & 3) << 2) + (w & 3);
    size_t prow = (size_t)win * 64 + pos;

    float gv[6], bv[6];
#pragma unroll
    for (int i = 0; i < 6; i++) { gv[i] = g[lane + 32*i]; bv[i] = b[lane + 32*i]; }

    const float* xr = x + (size_t)token * CEMB;
    const float* yr = y + (size_t)token * CEMB;
    float* xo = xn + prow * CEMB;
    float* yo = yn + prow * CEMB;

    {
        float v[6], s = 0.f, ss = 0.f;
#pragma unroll
        for (int i = 0; i < 6; i++) { v[i] = xr[lane + 32*i]; s += v[i]; ss += v[i]*v[i]; }
        warp_sum2(s, ss);
        float mean = s * (1.f/192.f);
        float var  = ss * (1.f/192.f) - mean * mean;
        float r = rsqrtf(var + 1e-5f);
#pragma unroll
        for (int i = 0; i < 6; i++) xo[lane + 32*i] = (v[i] - mean) * r * gv[i] + bv[i];
    }
    {
        float v[6], s = 0.f, ss = 0.f;
#pragma unroll
        for (int i = 0; i < 6; i++) { v[i] = yr[lane + 32*i]; s += v[i]; ss += v[i]*v[i]; }
        warp_sum2(s, ss);
        float mean = s * (1.f/192.f);
        float var  = ss * (1.f/192.f) - mean * mean;
        float r = rsqrtf(var + 1e-5f);
#pragma unroll
        for (int i = 0; i < 6; i++) yo[lane + 32*i] = (v[i] - mean) * r * gv[i] + bv[i];
    }
}

__global__ void __launch_bounds__(256) ln_kernel(
    const float* __restrict__ x, const float* __restrict__ g, const float* __restrict__ b,
    float* __restrict__ xn)
{
    int token = blockIdx.x * 8 + (threadIdx.x >> 5);
    int lane  = threadIdx.x & 31;
    const float* xr = x + (size_t)token * CEMB;
    float* xo = xn + (size_t)token * CEMB;
    float v[6], s = 0.f, ss = 0.f;
#pragma unroll
    for (int i = 0; i < 6; i++) { v[i] = xr[lane + 32*i]; s += v[i]; ss += v[i]*v[i]; }
    warp_sum2(s, ss);
    float mean = s * (1.f/192.f);
    float var  = ss * (1.f/192.f) - mean * mean;
    float r = rsqrtf(var + 1e-5f);
#pragma unroll
    for (int i = 0; i < 6; i++)
        xo[lane + 32*i] = (v[i] - mean) * r * g[lane + 32*i] + b[lane + 32*i];
}

// ---------------- bias table expansion (once per call, tiny) ---------------
__global__ void bias_expand_kernel(const float* __restrict__ rpb, float* __restrict__ bias)
{
    int head = blockIdx.x;
    for (int idx = threadIdx.x; idx < 64 * 64; idx += 256) {
        int i = idx >> 6, j = idx & 63;
        int iz = i >> 4, iy = (i >> 2) & 3, ix = i & 3;
        int jz = j >> 4, jy = (j >> 2) & 3, jx = j & 3;
        int ridx = (iz - jz + 3) * 49 + (iy - jy + 3) * 7 + (ix - jx + 3);
        bias[head * 4096 + idx] = rpb[ridx * NHEAD + head];
    }
}

// ---------------- mma helpers ----------------------------------------------
__device__ __forceinline__ float gelu_exact(float v) {
    return 0.5f * v * (1.0f + erff(v * 0.70710678118654752f));
}

__device__ __forceinline__ unsigned f2tf32(float f) {
    unsigned r;
    asm("cvt.rna.tf32.f32 %0, %1;" : "=r"(r) : "f"(f));
    return r;
}

__device__ __forceinline__ unsigned pack_bf16(float lo, float hi) {
    unsigned r;
    asm("cvt.rn.bf16x2.f32 %0, %1, %2;" : "=r"(r) : "f"(hi), "f"(lo));
    return r;
}

__device__ __forceinline__ void mma_tf32(float* c, const unsigned* a, const unsigned* b) {
    asm volatile(
        "mma.sync.aligned.m16n8k8.row.col.f32.tf32.tf32.f32 "
        "{%0,%1,%2,%3}, {%4,%5,%6,%7}, {%8,%9}, {%0,%1,%2,%3};"
        : "+f"(c[0]), "+f"(c[1]), "+f"(c[2]), "+f"(c[3])
        : "r"(a[0]), "r"(a[1]), "r"(a[2]), "r"(a[3]), "r"(b[0]), "r"(b[1]));
}

__device__ __forceinline__ void mma_bf16(float* c, const unsigned* a, const unsigned* b) {
    asm volatile(
        "mma.sync.aligned.m16n8k16.row.col.f32.bf16.bf16.f32 "
        "{%0,%1,%2,%3}, {%4,%5,%6,%7}, {%8,%9}, {%0,%1,%2,%3};"
        : "+f"(c[0]), "+f"(c[1]), "+f"(c[2]), "+f"(c[3])
        : "r"(a[0]), "r"(a[1]), "r"(a[2]), "r"(a[3]), "r"(b[0]), "r"(b[1]));
}

// ---------------- bf16 tensor-core GEMM ------------------------------------
// CTA tile 128 x (4*WN), BK=32 floats (16 bf16x2); 256 threads = 8 warps,
// warp tile 64 x WN. K packed in pairs along bf16x2 lanes.
// mode 0: C=(acc+bias)*scale; 1: window->natural permute + resid; 2: gelu; 3: +resid
template<int WN>
__global__ void __launch_bounds__(256) gemm_bf16_kernel(
    const float* __restrict__ A, const float* __restrict__ B,
    const float* __restrict__ bias, const float* __restrict__ resid,
    float* __restrict__ C,
    int K, int ldb, int ldc, float scale, int mode)
{
    constexpr int BN   = WN * 4;
    constexpr int LDB  = (WN == 16) ? 72 : 136;  // ≡8 mod 32 -> conflict-free frag reads
    constexpr int NF   = WN / 8;
    constexpr int BT   = BN / 64;                // B load tasks per thread (pair rows)

    __shared__ unsigned As[128][20];   // [row][k/2], 16 used + 4 pad
    __shared__ unsigned Bs[16][LDB];   // [k/2][n]

    int tid = threadIdx.x;
    int wid = tid >> 5, lane = tid & 31;
    int g = lane >> 2, t = lane & 3;
    int wm = (wid >> 2) * 64;
    int wn = (wid & 3) * WN;
    size_t rowBase = (size_t)blockIdx.y * 128;
    int nb = blockIdx.x * BN;

    // A: 4 float4 loads/thread
    int ar[4], ac[4];
#pragma unroll
    for (int it = 0; it < 4; it++) { int idx = tid + 256*it; ar[it] = idx >> 3; ac[it] = (idx & 7) * 4; }
    // B: BT tasks/thread; task = (k' , n-group of 4)
    int bk2[BT], bn0[BT];
#pragma unroll
    for (int it = 0; it < BT; it++) {
        int task = tid + 256*it;
        bk2[it] = task / (BN/4);
        bn0[it] = (task % (BN/4)) * 4;
    }

    float4 pa[4], pbe[BT], pbo[BT];
#pragma unroll
    for (int it = 0; it < 4; it++)
        pa[it] = *(const float4*)(A + (rowBase + ar[it]) * (size_t)K + ac[it]);
#pragma unroll
    for (int it = 0; it < BT; it++) {
        pbe[it] = *(const float4*)(B + (size_t)(2*bk2[it]    ) * ldb + nb + bn0[it]);
        pbo[it] = *(const float4*)(B + (size_t)(2*bk2[it] + 1) * ldb + nb + bn0[it]);
    }

    float acc[4][NF][4] = {};

    for (int k0 = 0; k0 < K; k0 += 32) {
#pragma unroll
        for (int it = 0; it < 4; it++) {
            uint2 u;
            u.x = pack_bf16(pa[it].x, pa[it].y);
            u.y = pack_bf16(pa[it].z, pa[it].w);
            *(uint2*)&As[ar[it]][ac[it] >> 1] = u;
        }
#pragma unroll
        for (int it = 0; it < BT; it++) {
            uint4 u;
            u.x = pack_bf16(pbe[it].x, pbo[it].x);
            u.y = pack_bf16(pbe[it].y, pbo[it].y);
            u.z = pack_bf16(pbe[it].z, pbo[it].z);
            u.w = pack_bf16(pbe[it].w, pbo[it].w);
            *(uint4*)&Bs[bk2[it]][bn0[it]] = u;
        }
        __syncthreads();

        if (k0 + 32 < K) {
            int kn = k0 + 32;
#pragma unroll
            for (int it = 0; it < 4; it++)
                pa[it] = *(const float4*)(A + (rowBase + ar[it]) * (size_t)K + kn + ac[it]);
#pragma unroll
            for (int it = 0; it < BT; it++) {
                pbe[it] = *(const float4*)(B + (size_t)(kn + 2*bk2[it]    ) * ldb + nb + bn0[it]);
                pbo[it] = *(const float4*)(B + (size_t)(kn + 2*bk2[it] + 1) * ldb + nb + bn0[it]);
            }
        }

#pragma unroll
        for (int ks = 0; ks < 2; ks++) {
            int kp = ks * 8;                   // packed k offset
            unsigned bf[NF][2];
#pragma unroll
            for (int nf = 0; nf < NF; nf++) {
                bf[nf][0] = Bs[kp + t    ][wn + nf*8 + g];
                bf[nf][1] = Bs[kp + t + 4][wn + nf*8 + g];
            }
#pragma unroll
            for (int mf = 0; mf < 4; mf++) {
                int r0 = wm + mf*16 + g;
                unsigned af[4];
                af[0] = As[r0    ][kp + t];
                af[1] = As[r0 + 8][kp + t];
                af[2] = As[r0    ][kp + t + 4];
                af[3] = As[r0 + 8][kp + t + 4];
#pragma unroll
                for (int nf = 0; nf < NF; nf++) mma_bf16(acc[mf][nf], af, bf[nf]);
            }
        }
        __syncthreads();
    }

#pragma unroll
    for (int mf = 0; mf < 4; mf++) {
#pragma unroll
        for (int half = 0; half < 2; half++) {
            size_t row = rowBase + wm + mf*16 + g + half*8;
            size_t orow = row;
            if (mode == 1) {
                int win = (int)(row >> 6), pos = (int)(row & 63);
                int wd = win >> 8, wh = (win >> 4) & 15, ww = win & 15;
                int d = (wd << 2) + (pos >> 4);
                int h = (wh << 2) + ((pos >> 2) & 3);
                int w = (ww << 2) + (pos & 3);
                orow = ((size_t)(d * 64 + h)) * 64 + w;
            }
#pragma unroll
            for (int nf = 0; nf < NF; nf++) {
                int col = nb + wn + nf*8 + 2*t;
                float v0 = acc[mf][nf][half*2+0] + bias[col];
                float v1 = acc[mf][nf][half*2+1] + bias[col+1];
                if (mode == 0) { v0 *= scale; v1 *= scale; }
                else if (mode == 1) {
                    v0 += resid[orow * CEMB + col];
                    v1 += resid[orow * CEMB + col + 1];
                } else if (mode == 2) {
                    v0 = gelu_exact(v0); v1 = gelu_exact(v1);
                } else {
                    v0 += resid[row * CEMB + col];
                    v1 += resid[row * CEMB + col + 1];
                }
                float2 o = make_float2(v0, v1);
                *(float2*)(C + orow * (size_t)ldc + col) = o;
            }
        }
    }
}

// ---------------- tensor-core windowed cross-attention ---------------------
// one block per (window, head); 128 threads (4 warps, 16 rows each)
__global__ void __launch_bounds__(128) attn_mma_kernel(
    const float* __restrict__ q, const float* __restrict__ kv,
    const float* __restrict__ bias, float* __restrict__ out)
{
    __shared__ unsigned sm_qk[64 * 36 * 2];   // Qs | Ks; reused as Ps[64][68]
    __shared__ unsigned sm_v [64 * 36];

    unsigned (*Qs)[36] = (unsigned(*)[36])sm_qk;
    unsigned (*Ks)[36] = (unsigned(*)[36])(sm_qk + 64*36);
    unsigned (*Ps)[68] = (unsigned(*)[68])sm_qk;
    unsigned (*Vs)[36] = (unsigned(*)[36])sm_v;

    int win = blockIdx.x, head = blockIdx.y;
    int tid = threadIdx.x;
    int wid = tid >> 5, lane = tid & 31;
    int g = lane >> 2, t = lane & 3;

    const float* qbase = q  + (size_t)win * 64 * CEMB   + head * HDIM;
    const float* kbase = kv + (size_t)win * 64 * 2*CEMB + head * HDIM;
    const float* vbase = kbase + CEMB;

    for (int idx = tid; idx < 64 * 32; idx += 128) {
        int r = idx >> 5, c = idx & 31;
        Qs[r][c] = f2tf32(qbase[(size_t)r * CEMB   + c]);
        Ks[r][c] = f2tf32(kbase[(size_t)r * 2*CEMB + c]);
        Vs[r][c] = f2tf32(vbase[(size_t)r * 2*CEMB + c]);
    }
    __syncthreads();

    // ---- S = Q K^T ----
    int r0 = wid * 16;
    float sacc[8][4] = {};
#pragma unroll
    for (int ks = 0; ks < 4; ks++) {
        int kk = ks * 8;
        unsigned af[4];
        af[0] = Qs[r0 + g    ][kk + t];
        af[1] = Qs[r0 + g + 8][kk + t];
        af[2] = Qs[r0 + g    ][kk + t + 4];
        af[3] = Qs[r0 + g + 8][kk + t + 4];
#pragma unroll
        for (int nt = 0; nt < 8; nt++) {
            unsigned bf[2];
            bf[0] = Ks[nt*8 + g][kk + t];
            bf[1] = Ks[nt*8 + g][kk + t + 4];
            mma_tf32(sacc[nt], af, bf);
        }
    }
    __syncthreads();

    // ---- bias + softmax (rows rA, rB) ----
    int rA = r0 + g, rB = rA + 8;
    const float* bA = bias + head * 4096 + rA * 64;
    const float* bB = bias + head * 4096 + rB * 64;

    float vA[16], vB[16];
    float mA = -1e30f, mB = -1e30f;
#pragma unroll
    for (int nt = 0; nt < 8; nt++) {
#pragma unroll
        for (int e = 0; e < 2; e++) {
            int j = nt*8 + 2*t + e;
            float a = sacc[nt][e]     + bA[j];
            float b = sacc[nt][2 + e] + bB[j];
            vA[nt*2+e] = a; mA = fmaxf(mA, a);
            vB[nt*2+e] = b; mB = fmaxf(mB, b);
        }
    }
    mA = fmaxf(mA, __shfl_xor_sync(0xffffffffu, mA, 1));
    mA = fmaxf(mA, __shfl_xor_sync(0xffffffffu, mA, 2));
    mB = fmaxf(mB, __shfl_xor_sync(0xffffffffu, mB, 1));
    mB = fmaxf(mB, __shfl_xor_sync(0xffffffffu, mB, 2));

    float sA = 0.f, sB = 0.f;
#pragma unroll
    for (int i = 0; i < 16; i++) {
        vA[i] = __expf(vA[i] - mA); sA += vA[i];
        vB[i] = __expf(vB[i] - mB); sB += vB[i];
    }
    sA += __shfl_xor_sync(0xffffffffu, sA, 1);
    sA += __shfl_xor_sync(0xffffffffu, sA, 2);
    sB += __shfl_xor_sync(0xffffffffu, sB, 1);
    sB += __shfl_xor_sync(0xffffffffu, sB, 2);
    float rAi = 1.f / sA, rBi = 1.f / sB;

#pragma unroll
    for (int nt = 0; nt < 8; nt++) {
#pragma unroll
        for (int e = 0; e < 2; e++) {
            int j = nt*8 + 2*t + e;
            Ps[rA][j] = f2tf32(vA[nt*2+e] * rAi);
            Ps[rB][j] = f2tf32(vB[nt*2+e] * rBi);
        }
    }
    __syncwarp();

    // ---- O = P V ----
    float oacc[4][4] = {};
#pragma unroll
    for (int ks = 0; ks < 8; ks++) {
        int kk = ks * 8;
        unsigned af[4];
        af[0] = Ps[r0 + g    ][kk + t];
        af[1] = Ps[r0 + g + 8][kk + t];
        af[2] = Ps[r0 + g    ][kk + t + 4];
        af[3] = Ps[r0 + g + 8][kk + t + 4];
#pragma unroll
        for (int nt = 0; nt < 4; nt++) {
            unsigned bf[2];
            bf[0] = Vs[kk + t    ][nt*8 + g];
            bf[1] = Vs[kk + t + 4][nt*8 + g];
            mma_tf32(oacc[nt], af, bf);
        }
    }

    float* obase = out + (size_t)win * 64 * CEMB + head * HDIM;
#pragma unroll
    for (int nt = 0; nt < 4; nt++) {
        int c = nt*8 + 2*t;
        *(float2*)&obase[(size_t)rA * CEMB + c] = make_float2(oacc[nt][0], oacc[nt][1]);
        *(float2*)&obase[(size_t)rB * CEMB + c] = make_float2(oacc[nt][2], oacc[nt][3]);
    }
}

// ---------------- launch ----------------------------------------------------
extern "C" void kernel_launch(void* const* d_in, const int* in_sizes, int n_in,
                              void* d_out, int out_size)
{
    const float* x     = (const float*)d_in[0];
    const float* y     = (const float*)d_in[1];
    const float* n1g   = (const float*)d_in[3];
    const float* n1b   = (const float*)d_in[4];
    const float* qkvw  = (const float*)d_in[5];
    const float* qkvb  = (const float*)d_in[6];
    const float* rpb   = (const float*)d_in[7];
    const float* projw = (const float*)d_in[8];
    const float* projb = (const float*)d_in[9];
    const float* n2g   = (const float*)d_in[10];
    const float* n2b   = (const float*)d_in[11];
    const float* fc1w  = (const float*)d_in[12];
    const float* fc1b  = (const float*)d_in[13];
    const float* fc2w  = (const float*)d_in[14];
    const float* fc2b  = (const float*)d_in[15];
    float* out = (float*)d_out;

    float *xn, *yn, *qb, *kvb, *ao, *x1, *xn2, *hb, *bexp;
    cudaGetSymbolAddress((void**)&xn,  g_xn);
    cudaGetSymbolAddress((void**)&yn,  g_yn);
    cudaGetSymbolAddress((void**)&qb,  g_q);
    cudaGetSymbolAddress((void**)&kvb, g_kv);
    cudaGetSymbolAddress((void**)&ao,  g_ao);
    cudaGetSymbolAddress((void**)&x1,  g_x1);
    cudaGetSymbolAddress((void**)&xn2, g_xn2);
    cudaGetSymbolAddress((void**)&hb,  g_h);
    cudaGetSymbolAddress((void**)&bexp, g_bias);

    // 0) expand relative-position bias table (tiny)
    bias_expand_kernel<<<NHEAD, 256>>>(rpb, bexp);

    // 1) LN1 + window permutation for x and y
    ln_perm_kernel<<<TOKENS / 8, 256>>>(x, y, n1g, n1b, xn, yn);

    // 2) Q = (yn @ Wq + bq) * SCALE   (window order)
    gemm_bf16_kernel<16><<<dim3(3, TOKENS / 128), 256>>>(yn, qkvw, qkvb, nullptr, qb,
                                                         192, 576, 192, QSCALE, 0);
    // 3) KV = xn @ W[k|v] + b         (window order)
    gemm_bf16_kernel<16><<<dim3(6, TOKENS / 128), 256>>>(xn, qkvw + 192, qkvb + 192, nullptr, kvb,
                                                         192, 576, 384, 1.0f, 0);
    // 4) window attention (tensor cores)
    attn_mma_kernel<<<dim3(NWIN, NHEAD), 128>>>(qb, kvb, bexp, ao);

    // 5) x1 = x + attn_out @ proj_w + proj_b  (un-permute to natural order)
    gemm_bf16_kernel<16><<<dim3(3, TOKENS / 128), 256>>>(ao, projw, projb, x, x1,
                                                         192, 192, 192, 1.0f, 1);
    // 6) LN2
    ln_kernel<<<TOKENS / 8, 256>>>(x1, n2g, n2b, xn2);

    // 7) h = gelu(xn2 @ fc1_w + fc1_b)   (wide-N tile)
    gemm_bf16_kernel<32><<<dim3(6, TOKENS / 128), 256>>>(xn2, fc1w, fc1b, nullptr, hb,
                                                         192, 768, 768, 1.0f, 2);
    // 8) out = x1 + h @ fc2_w + fc2_b
    gemm_bf16_kernel<16><<<dim3(3, TOKENS / 128), 256>>>(hb, fc2w, fc2b, x1, out,
                                                         768, 192, 192, 1.0f, 3);
}

// round 7
// speedup vs baseline: 3.6257x; 1.0418x over previous
#include <cuda_runtime.h>
#include <math.h>

#define TOKENS 131072
#define CEMB   192
#define NHEAD  6
#define HDIM   32
#define NWIN   2048
#define QSCALE 0.17677669529663687f  // 1/sqrt(32)

// ---------------- scratch (device globals; no runtime allocation) ----------
__device__ float g_xn [(size_t)TOKENS * CEMB];   // LN1(x), window order
__device__ float g_yn [(size_t)TOKENS * CEMB];   // LN1(y), window order
__device__ float g_q  [(size_t)TOKENS * CEMB];   // scaled Q (from y), window order
__device__ float g_kv [(size_t)TOKENS * 2*CEMB]; // [row][0:192]=K, [192:384]=V, window order
__device__ float g_ao [(size_t)TOKENS * CEMB];   // attention out (head-concat), window order
__device__ float g_x1 [(size_t)TOKENS * CEMB];   // x + proj(attn), natural order
__device__ float g_xn2[(size_t)TOKENS * CEMB];   // LN2(x1), natural order
__device__ float g_h  [(size_t)TOKENS * 768];    // MLP hidden
__device__ float g_bias[NHEAD * 64 * 64];        // expanded relative-position bias

// ---------------- LayerNorm (float4, + window permutation) -----------------
__device__ __forceinline__ void warp_sum2(float& s, float& ss) {
#pragma unroll
    for (int o = 16; o; o >>= 1) {
        s  += __shfl_xor_sync(0xffffffffu, s,  o);
        ss += __shfl_xor_sync(0xffffffffu, ss, o);
    }
}

// one warp per token; 48 float4 per row: lane does f4[lane], lanes<16 also f4[32+lane]
__device__ __forceinline__ void ln_row_f4(
    const float4* __restrict__ in, float4* __restrict__ outp,
    float4 g0, float4 b0, float4 g1, float4 b1, int lane, bool hi)
{
    float4 a = in[lane];
    float4 c = hi ? in[32 + lane] : make_float4(0.f, 0.f, 0.f, 0.f);
    float s  = a.x + a.y + a.z + a.w + c.x + c.y + c.z + c.w;
    float ss = a.x*a.x + a.y*a.y + a.z*a.z + a.w*a.w
             + c.x*c.x + c.y*c.y + c.z*c.z + c.w*c.w;
    warp_sum2(s, ss);
    float mean = s * (1.f/192.f);
    float var  = ss * (1.f/192.f) - mean * mean;
    float r = rsqrtf(var + 1e-5f);
    float4 o;
    o.x = (a.x - mean) * r * g0.x + b0.x;
    o.y = (a.y - mean) * r * g0.y + b0.y;
    o.z = (a.z - mean) * r * g0.z + b0.z;
    o.w = (a.w - mean) * r * g0.w + b0.w;
    outp[lane] = o;
    if (hi) {
        float4 p;
        p.x = (c.x - mean) * r * g1.x + b1.x;
        p.y = (c.y - mean) * r * g1.y + b1.y;
        p.z = (c.z - mean) * r * g1.z + b1.z;
        p.w = (c.w - mean) * r * g1.w + b1.w;
        outp[32 + lane] = p;
    }
}

__global__ void __launch_bounds__(256) ln_perm_kernel(
    const float* __restrict__ x, const float* __restrict__ y,
    const float* __restrict__ g, const float* __restrict__ b,
    float* __restrict__ xn, float* __restrict__ yn)
{
    int token = blockIdx.x * 8 + (threadIdx.x >> 5);
    int lane  = threadIdx.x & 31;
    bool hi = lane < 16;
    int w = token & 63, h = (token >> 6) & 63, d = token >> 12;
    int win  = (((d >> 2) << 4) + (h >> 2)) * 16 + (w >> 2);
    int pos  = ((d & 3) << 4) + ((h & 3) << 2) + (w & 3);
    size_t prow = (size_t)win * 64 + pos;

    const float4* g4 = (const float4*)g;
    const float4* b4 = (const float4*)b;
    float4 g0 = g4[lane], b0 = b4[lane];
    float4 g1 = make_float4(0,0,0,0), b1 = g1;
    if (hi) { g1 = g4[32 + lane]; b1 = b4[32 + lane]; }

    ln_row_f4((const float4*)(x + (size_t)token * CEMB),
              (float4*)(xn + prow * CEMB), g0, b0, g1, b1, lane, hi);
    ln_row_f4((const float4*)(y + (size_t)token * CEMB),
              (float4*)(yn + prow * CEMB), g0, b0, g1, b1, lane, hi);
}

__global__ void __launch_bounds__(256) ln_kernel(
    const float* __restrict__ x, const float* __restrict__ g, const float* __restrict__ b,
    float* __restrict__ xn)
{
    int token = blockIdx.x * 8 + (threadIdx.x >> 5);
    int lane  = threadIdx.x & 31;
    bool hi = lane < 16;
    const float4* g4 = (const float4*)g;
    const float4* b4 = (const float4*)b;
    float4 g0 = g4[lane], b0 = b4[lane];
    float4 g1 = make_float4(0,0,0,0), b1 = g1;
    if (hi) { g1 = g4[32 + lane]; b1 = b4[32 + lane]; }
    ln_row_f4((const float4*)(x + (size_t)token * CEMB),
              (float4*)(xn + (size_t)token * CEMB), g0, b0, g1, b1, lane, hi);
}

// ---------------- bias table expansion (once per call, tiny) ---------------
__global__ void bias_expand_kernel(const float* __restrict__ rpb, float* __restrict__ bias)
{
    int head = blockIdx.x;
    for (int idx = threadIdx.x; idx < 64 * 64; idx += 256) {
        int i = idx >> 6, j = idx & 63;
        int iz = i >> 4, iy = (i >> 2) & 3, ix = i & 3;
        int jz = j >> 4, jy = (j >> 2) & 3, jx = j & 3;
        int ridx = (iz - jz + 3) * 49 + (iy - jy + 3) * 7 + (ix - jx + 3);
        bias[head * 4096 + idx] = rpb[ridx * NHEAD + head];
    }
}

// ---------------- mma helpers ----------------------------------------------
__device__ __forceinline__ float gelu_exact(float v) {
    return 0.5f * v * (1.0f + erff(v * 0.70710678118654752f));
}

__device__ __forceinline__ unsigned f2tf32(float f) {
    unsigned r;
    asm("cvt.rna.tf32.f32 %0, %1;" : "=r"(r) : "f"(f));
    return r;
}

__device__ __forceinline__ unsigned pack_bf16(float lo, float hi) {
    unsigned r;
    asm("cvt.rn.bf16x2.f32 %0, %1, %2;" : "=r"(r) : "f"(hi), "f"(lo));
    return r;
}

__device__ __forceinline__ void mma_tf32(float* c, const unsigned* a, const unsigned* b) {
    asm volatile(
        "mma.sync.aligned.m16n8k8.row.col.f32.tf32.tf32.f32 "
        "{%0,%1,%2,%3}, {%4,%5,%6,%7}, {%8,%9}, {%0,%1,%2,%3};"
        : "+f"(c[0]), "+f"(c[1]), "+f"(c[2]), "+f"(c[3])
        : "r"(a[0]), "r"(a[1]), "r"(a[2]), "r"(a[3]), "r"(b[0]), "r"(b[1]));
}

__device__ __forceinline__ void mma_bf16(float* c, const unsigned* a, const unsigned* b) {
    asm volatile(
        "mma.sync.aligned.m16n8k16.row.col.f32.bf16.bf16.f32 "
        "{%0,%1,%2,%3}, {%4,%5,%6,%7}, {%8,%9}, {%0,%1,%2,%3};"
        : "+f"(c[0]), "+f"(c[1]), "+f"(c[2]), "+f"(c[3])
        : "r"(a[0]), "r"(a[1]), "r"(a[2]), "r"(a[3]), "r"(b[0]), "r"(b[1]));
}

// ---------------- bf16 tensor-core GEMM ------------------------------------
// CTA tile 128 x (4*WN), BK=32 floats; 256 threads = 8 warps (2x4), warp 64 x WN.
// WN in {24, 32}. K packed in pairs along bf16x2 lanes.
// mode 0: C=(acc+bias)*scale; 1: window->natural permute + resid; 2: gelu; 3: +resid
template<int WN>
__global__ void __launch_bounds__(256) gemm_bf16_kernel(
    const float* __restrict__ A, const float* __restrict__ B,
    const float* __restrict__ bias, const float* __restrict__ resid,
    float* __restrict__ C,
    int K, int ldb, int ldc, float scale, int mode)
{
    constexpr int BN    = WN * 4;
    constexpr int LDB   = BN + 8;                 // ≡8 mod 32 -> conflict-free frag reads
    constexpr int NF    = WN / 8;
    constexpr int BTASK = (16 * (BN / 2)) / 256;  // B float2-pair tasks per thread

    __shared__ unsigned As[128][20];   // [row][k/2], 16 used + 4 pad
    __shared__ unsigned Bs[16][LDB];   // [k/2][n]

    int tid = threadIdx.x;
    int wid = tid >> 5, lane = tid & 31;
    int g = lane >> 2, t = lane & 3;
    int wm = (wid >> 2) * 64;
    int wn = (wid & 3) * WN;
    size_t rowBase = (size_t)blockIdx.y * 128;
    int nb = blockIdx.x * BN;

    // A: 4 float4 loads/thread
    int ar[4], ac[4];
#pragma unroll
    for (int it = 0; it < 4; it++) { int idx = tid + 256*it; ar[it] = idx >> 3; ac[it] = (idx & 7) * 4; }
    // B: BTASK tasks/thread; task = (k-pair row, 2-col group)
    int bk2[BTASK], bn0[BTASK];
#pragma unroll
    for (int it = 0; it < BTASK; it++) {
        int task = tid + 256*it;
        bk2[it] = task / (BN/2);
        bn0[it] = (task % (BN/2)) * 2;
    }

    float4 pa[4];
    float2 pbe[BTASK], pbo[BTASK];
#pragma unroll
    for (int it = 0; it < 4; it++)
        pa[it] = *(const float4*)(A + (rowBase + ar[it]) * (size_t)K + ac[it]);
#pragma unroll
    for (int it = 0; it < BTASK; it++) {
        pbe[it] = *(const float2*)(B + (size_t)(2*bk2[it]    ) * ldb + nb + bn0[it]);
        pbo[it] = *(const float2*)(B + (size_t)(2*bk2[it] + 1) * ldb + nb + bn0[it]);
    }

    float acc[4][NF][4] = {};

    for (int k0 = 0; k0 < K; k0 += 32) {
#pragma unroll
        for (int it = 0; it < 4; it++) {
            uint2 u;
            u.x = pack_bf16(pa[it].x, pa[it].y);
            u.y = pack_bf16(pa[it].z, pa[it].w);
            *(uint2*)&As[ar[it]][ac[it] >> 1] = u;
        }
#pragma unroll
        for (int it = 0; it < BTASK; it++) {
            uint2 u;
            u.x = pack_bf16(pbe[it].x, pbo[it].x);
            u.y = pack_bf16(pbe[it].y, pbo[it].y);
            *(uint2*)&Bs[bk2[it]][bn0[it]] = u;
        }
        __syncthreads();

        if (k0 + 32 < K) {
            int kn = k0 + 32;
#pragma unroll
            for (int it = 0; it < 4; it++)
                pa[it] = *(const float4*)(A + (rowBase + ar[it]) * (size_t)K + kn + ac[it]);
#pragma unroll
            for (int it = 0; it < BTASK; it++) {
                pbe[it] = *(const float2*)(B + (size_t)(kn + 2*bk2[it]    ) * ldb + nb + bn0[it]);
                pbo[it] = *(const float2*)(B + (size_t)(kn + 2*bk2[it] + 1) * ldb + nb + bn0[it]);
            }
        }

#pragma unroll
        for (int ks = 0; ks < 2; ks++) {
            int kp = ks * 8;                   // packed k offset
            unsigned bf[NF][2];
#pragma unroll
            for (int nf = 0; nf < NF; nf++) {
                bf[nf][0] = Bs[kp + t    ][wn + nf*8 + g];
                bf[nf][1] = Bs[kp + t + 4][wn + nf*8 + g];
            }
#pragma unroll
            for (int mf = 0; mf < 4; mf++) {
                int r0 = wm + mf*16 + g;
                unsigned af[4];
                af[0] = As[r0    ][kp + t];
                af[1] = As[r0 + 8][kp + t];
                af[2] = As[r0    ][kp + t + 4];
                af[3] = As[r0 + 8][kp + t + 4];
#pragma unroll
                for (int nf = 0; nf < NF; nf++) mma_bf16(acc[mf][nf], af, bf[nf]);
            }
        }
        __syncthreads();
    }

#pragma unroll
    for (int mf = 0; mf < 4; mf++) {
#pragma unroll
        for (int half = 0; half < 2; half++) {
            size_t row = rowBase + wm + mf*16 + g + half*8;
            size_t orow = row;
            if (mode == 1) {
                int win = (int)(row >> 6), pos = (int)(row & 63);
                int wd = win >> 8, wh = (win >> 4) & 15, ww = win & 15;
                int d = (wd << 2) + (pos >> 4);
                int h = (wh << 2) + ((pos >> 2) & 3);
                int w = (ww << 2) + (pos & 3);
                orow = ((size_t)(d * 64 + h)) * 64 + w;
            }
#pragma unroll
            for (int nf = 0; nf < NF; nf++) {
                int col = nb + wn + nf*8 + 2*t;
                float v0 = acc[mf][nf][half*2+0] + bias[col];
                float v1 = acc[mf][nf][half*2+1] + bias[col+1];
                if (mode == 0) { v0 *= scale; v1 *= scale; }
                else if (mode == 1) {
                    v0 += resid[orow * CEMB + col];
                    v1 += resid[orow * CEMB + col + 1];
                } else if (mode == 2) {
                    v0 = gelu_exact(v0); v1 = gelu_exact(v1);
                } else {
                    v0 += resid[row * CEMB + col];
                    v1 += resid[row * CEMB + col + 1];
                }
                float2 o = make_float2(v0, v1);
                *(float2*)(C + orow * (size_t)ldc + col) = o;
            }
        }
    }
}

// ---------------- tensor-core windowed cross-attention ---------------------
// one block per (window, head); 128 threads (4 warps, 16 rows each)
__global__ void __launch_bounds__(128) attn_mma_kernel(
    const float* __restrict__ q, const float* __restrict__ kv,
    const float* __restrict__ bias, float* __restrict__ out)
{
    __shared__ unsigned sm_qk[64 * 36 * 2];   // Qs | Ks; reused as Ps[64][68]
    __shared__ unsigned sm_v [64 * 36];

    unsigned (*Qs)[36] = (unsigned(*)[36])sm_qk;
    unsigned (*Ks)[36] = (unsigned(*)[36])(sm_qk + 64*36);
    unsigned (*Ps)[68] = (unsigned(*)[68])sm_qk;
    unsigned (*Vs)[36] = (unsigned(*)[36])sm_v;

    int win = blockIdx.x, head = blockIdx.y;
    int tid = threadIdx.x;
    int wid = tid >> 5, lane = tid & 31;
    int g = lane >> 2, t = lane & 3;

    const float* qbase = q  + (size_t)win * 64 * CEMB   + head * HDIM;
    const float* kbase = kv + (size_t)win * 64 * 2*CEMB + head * HDIM;
    const float* vbase = kbase + CEMB;

    for (int idx = tid; idx < 64 * 32; idx += 128) {
        int r = idx >> 5, c = idx & 31;
        Qs[r][c] = f2tf32(qbase[(size_t)r * CEMB   + c]);
        Ks[r][c] = f2tf32(kbase[(size_t)r * 2*CEMB + c]);
        Vs[r][c] = f2tf32(vbase[(size_t)r * 2*CEMB + c]);
    }
    __syncthreads();

    // ---- S = Q K^T ----
    int r0 = wid * 16;
    float sacc[8][4] = {};
#pragma unroll
    for (int ks = 0; ks < 4; ks++) {
        int kk = ks * 8;
        unsigned af[4];
        af[0] = Qs[r0 + g    ][kk + t];
        af[1] = Qs[r0 + g + 8][kk + t];
        af[2] = Qs[r0 + g    ][kk + t + 4];
        af[3] = Qs[r0 + g + 8][kk + t + 4];
#pragma unroll
        for (int nt = 0; nt < 8; nt++) {
            unsigned bf[2];
            bf[0] = Ks[nt*8 + g][kk + t];
            bf[1] = Ks[nt*8 + g][kk + t + 4];
            mma_tf32(sacc[nt], af, bf);
        }
    }
    __syncthreads();

    // ---- bias + softmax (rows rA, rB) ----
    int rA = r0 + g, rB = rA + 8;
    const float* bA = bias + head * 4096 + rA * 64;
    const float* bB = bias + head * 4096 + rB * 64;

    float vA[16], vB[16];
    float mA = -1e30f, mB = -1e30f;
#pragma unroll
    for (int nt = 0; nt < 8; nt++) {
#pragma unroll
        for (int e = 0; e < 2; e++) {
            int j = nt*8 + 2*t + e;
            float a = sacc[nt][e]     + bA[j];
            float b = sacc[nt][2 + e] + bB[j];
            vA[nt*2+e] = a; mA = fmaxf(mA, a);
            vB[nt*2+e] = b; mB = fmaxf(mB, b);
        }
    }
    mA = fmaxf(mA, __shfl_xor_sync(0xffffffffu, mA, 1));
    mA = fmaxf(mA, __shfl_xor_sync(0xffffffffu, mA, 2));
    mB = fmaxf(mB, __shfl_xor_sync(0xffffffffu, mB, 1));
    mB = fmaxf(mB, __shfl_xor_sync(0xffffffffu, mB, 2));

    float sA = 0.f, sB = 0.f;
#pragma unroll
    for (int i = 0; i < 16; i++) {
        vA[i] = __expf(vA[i] - mA); sA += vA[i];
        vB[i] = __expf(vB[i] - mB); sB += vB[i];
    }
    sA += __shfl_xor_sync(0xffffffffu, sA, 1);
    sA += __shfl_xor_sync(0xffffffffu, sA, 2);
    sB += __shfl_xor_sync(0xffffffffu, sB, 1);
    sB += __shfl_xor_sync(0xffffffffu, sB, 2);
    float rAi = 1.f / sA, rBi = 1.f / sB;

#pragma unroll
    for (int nt = 0; nt < 8; nt++) {
#pragma unroll
        for (int e = 0; e < 2; e++) {
            int j = nt*8 + 2*t + e;
            Ps[rA][j] = f2tf32(vA[nt*2+e] * rAi);
            Ps[rB][j] = f2tf32(vB[nt*2+e] * rBi);
        }
    }
    __syncwarp();

    // ---- O = P V ----
    float oacc[4][4] = {};
#pragma unroll
    for (int ks = 0; ks < 8; ks++) {
        int kk = ks * 8;
        unsigned af[4];
        af[0] = Ps[r0 + g    ][kk + t];
        af[1] = Ps[r0 + g + 8][kk + t];
        af[2] = Ps[r0 + g    ][kk + t + 4];
        af[3] = Ps[r0 + g + 8][kk + t + 4];
#pragma unroll
        for (int nt = 0; nt < 4; nt++) {
            unsigned bf[2];
            bf[0] = Vs[kk + t    ][nt*8 + g];
            bf[1] = Vs[kk + t + 4][nt*8 + g];
            mma_tf32(oacc[nt], af, bf);
        }
    }

    float* obase = out + (size_t)win * 64 * CEMB + head * HDIM;
#pragma unroll
    for (int nt = 0; nt < 4; nt++) {
        int c = nt*8 + 2*t;
        *(float2*)&obase[(size_t)rA * CEMB + c] = make_float2(oacc[nt][0], oacc[nt][1]);
        *(float2*)&obase[(size_t)rB * CEMB + c] = make_float2(oacc[nt][2], oacc[nt][3]);
    }
}

// ---------------- launch ----------------------------------------------------
extern "C" void kernel_launch(void* const* d_in, const int* in_sizes, int n_in,
                              void* d_out, int out_size)
{
    const float* x     = (const float*)d_in[0];
    const float* y     = (const float*)d_in[1];
    const float* n1g   = (const float*)d_in[3];
    const float* n1b   = (const float*)d_in[4];
    const float* qkvw  = (const float*)d_in[5];
    const float* qkvb  = (const float*)d_in[6];
    const float* rpb   = (const float*)d_in[7];
    const float* projw = (const float*)d_in[8];
    const float* projb = (const float*)d_in[9];
    const float* n2g   = (const float*)d_in[10];
    const float* n2b   = (const float*)d_in[11];
    const float* fc1w  = (const float*)d_in[12];
    const float* fc1b  = (const float*)d_in[13];
    const float* fc2w  = (const float*)d_in[14];
    const float* fc2b  = (const float*)d_in[15];
    float* out = (float*)d_out;

    float *xn, *yn, *qb, *kvb, *ao, *x1, *xn2, *hb, *bexp;
    cudaGetSymbolAddress((void**)&xn,  g_xn);
    cudaGetSymbolAddress((void**)&yn,  g_yn);
    cudaGetSymbolAddress((void**)&qb,  g_q);
    cudaGetSymbolAddress((void**)&kvb, g_kv);
    cudaGetSymbolAddress((void**)&ao,  g_ao);
    cudaGetSymbolAddress((void**)&x1,  g_x1);
    cudaGetSymbolAddress((void**)&xn2, g_xn2);
    cudaGetSymbolAddress((void**)&hb,  g_h);
    cudaGetSymbolAddress((void**)&bexp, g_bias);

    // 0) expand relative-position bias table (tiny)
    bias_expand_kernel<<<NHEAD, 256>>>(rpb, bexp);

    // 1) LN1 + window permutation for x and y
    ln_perm_kernel<<<TOKENS / 8, 256>>>(x, y, n1g, n1b, xn, yn);

    // 2) Q = (yn @ Wq + bq) * SCALE   (window order)  N=192 -> WN24, grid.x=2
    gemm_bf16_kernel<24><<<dim3(2, TOKENS / 128), 256>>>(yn, qkvw, qkvb, nullptr, qb,
                                                         192, 576, 192, QSCALE, 0);
    // 3) KV = xn @ W[k|v] + b         (window order)  N=384 -> WN32, grid.x=3
    gemm_bf16_kernel<32><<<dim3(3, TOKENS / 128), 256>>>(xn, qkvw + 192, qkvb + 192, nullptr, kvb,
                                                         192, 576, 384, 1.0f, 0);
    // 4) window attention (tensor cores)
    attn_mma_kernel<<<dim3(NWIN, NHEAD), 128>>>(qb, kvb, bexp, ao);

    // 5) x1 = x + attn_out @ proj_w + proj_b  (un-permute)  N=192 -> WN24
    gemm_bf16_kernel<24><<<dim3(2, TOKENS / 128), 256>>>(ao, projw, projb, x, x1,
                                                         192, 192, 192, 1.0f, 1);
    // 6) LN2
    ln_kernel<<<TOKENS / 8, 256>>>(x1, n2g, n2b, xn2);

    // 7) h = gelu(xn2 @ fc1_w + fc1_b)   N=768 -> WN32, grid.x=6
    gemm_bf16_kernel<32><<<dim3(6, TOKENS / 128), 256>>>(xn2, fc1w, fc1b, nullptr, hb,
                                                         192, 768, 768, 1.0f, 2);
    // 8) out = x1 + h @ fc2_w + fc2_b    N=192 -> WN24
    gemm_bf16_kernel<24><<<dim3(2, TOKENS / 128), 256>>>(hb, fc2w, fc2b, x1, out,
                                                         768, 192, 192, 1.0f, 3);
}